// round 6
// baseline (speedup 1.0000x reference)
#include <cuda_runtime.h>
#include <cstdint>

// ---------------- problem constants ----------------
#define DK 1024
#define DN 1024
#define NEXP 32
#define MAX_TILES 1056

// ---------------- GEMM tiling ----------------
#define BM 128
#define BN 128
#define BK 32
#define STAGES 3
#define NK (DK / BK)        // 32 k-stages
#define PAD 4
#define LDA (BK + PAD)      // 36 floats per smem row -> conflict-free frag loads
#define A_STAGE_F (BM * LDA)    // 4608 floats
#define B_STAGE_F (BN * LDA)
#define SMEM_FLOATS (STAGES * (A_STAGE_F + B_STAGE_F) + BN)
#define SMEM_BYTES (SMEM_FLOATS * 4)   // 111,104 B

// warp layout: 8 warps = 2 (M) x 4 (N); warp tile 64x32
#define WARP_M 64
#define WARP_N 32
#define MITER (WARP_M / 16)   // 4
#define NITER (WARP_N / 8)    // 4

// ---------------- device metadata scratch ----------------
__device__ int g_tile_expert[MAX_TILES];
__device__ int g_tile_row0[MAX_TILES];
__device__ int g_tile_rows[MAX_TILES];
__device__ int g_num_tiles;

// ---------------- helpers ----------------
__device__ __forceinline__ uint32_t smem_u32(const void* p) {
    uint32_t a;
    asm("{ .reg .u64 t; cvta.to.shared.u64 t, %1; cvt.u32.u64 %0, t; }" : "=r"(a) : "l"(p));
    return a;
}
__device__ __forceinline__ void cp_async16(uint32_t dst, const void* src) {
    asm volatile("cp.async.cg.shared.global [%0], [%1], 16;" :: "r"(dst), "l"(src) : "memory");
}
__device__ __forceinline__ void cp_commit() {
    asm volatile("cp.async.commit_group;" ::: "memory");
}
__device__ __forceinline__ void cp_wait1() {
    asm volatile("cp.async.wait_group 1;" ::: "memory");
}
__device__ __forceinline__ uint32_t rna_tf32_u(uint32_t u) {
    uint32_t r;
    asm("cvt.rna.tf32.f32 %0, %1;" : "=r"(r) : "r"(u));
    return r;
}
__device__ __forceinline__ void mma_tf32(float& c0, float& c1, float& c2, float& c3,
                                         uint32_t a0, uint32_t a1, uint32_t a2, uint32_t a3,
                                         uint32_t b0, uint32_t b1) {
    asm volatile(
        "mma.sync.aligned.m16n8k8.row.col.f32.tf32.tf32.f32 "
        "{%0,%1,%2,%3}, {%4,%5,%6,%7}, {%8,%9}, {%0,%1,%2,%3};"
        : "+f"(c0), "+f"(c1), "+f"(c2), "+f"(c3)
        : "r"(a0), "r"(a1), "r"(a2), "r"(a3), "r"(b0), "r"(b1));
}

// ---------------- kernel 1: tile metadata ----------------
__global__ void meta_kernel(const void* __restrict__ freqv, int T) {
    if (threadIdx.x != 0 || blockIdx.x != 0) return;
    const int* f32p = (const int*)freqv;
    const long long* f64p = (const long long*)freqv;
    long long s32 = 0;
    for (int i = 0; i < NEXP; i++) s32 += f32p[i];
    const bool is64 = (s32 != (long long)T);
    int nt = 0, off = 0;
    for (int e = 0; e < NEXP; e++) {
        int c = is64 ? (int)f64p[e] : f32p[e];
        for (int r = 0; r < c; r += BM) {
            g_tile_expert[nt] = e;
            g_tile_row0[nt] = off + r;
            g_tile_rows[nt] = (c - r < BM) ? (c - r) : BM;
            nt++;
        }
        off += c;
    }
    g_num_tiles = nt;
}

// ---------------- kernel 2: grouped GEMM (tf32 mma.sync) ----------------
__global__ void __launch_bounds__(256, 2) gemm_kernel(
    const float* __restrict__ x,      // [T, DK]
    const float* __restrict__ w,      // [NEXP, DN, DK] -> rows of [NEXP*DN, DK]
    const float* __restrict__ bias,   // [NEXP, DN]
    float* __restrict__ out,          // [T, DN]
    int T)
{
    extern __shared__ float smem[];
    float* As = smem;                               // [STAGES][BM][LDA]
    float* Bs = smem + STAGES * A_STAGE_F;          // [STAGES][BN][LDA]
    float* bias_s = Bs + STAGES * B_STAGE_F;        // [BN]

    const int tile = blockIdx.y;
    if (tile >= g_num_tiles) return;

    const int n0 = blockIdx.x * BN;
    const int e = g_tile_expert[tile];
    const int row0 = g_tile_row0[tile];
    const int rows = g_tile_rows[tile];

    const int tid = threadIdx.x;
    const int lane = tid & 31;
    const int wid = tid >> 5;
    const int warp_m = wid & 1;        // 0..1
    const int warp_n = wid >> 1;       // 0..3

    const uint32_t As_u = smem_u32(As);
    const uint32_t Bs_u = smem_u32(Bs);

    if (tid < BN) bias_s[tid] = bias[e * DN + n0 + tid];

    // ---- stage loader: 1024 16B-chunks for A, 1024 for B; 256 threads x 4 each ----
    // chunk c: row = c>>3, kc = c&7 (4 floats per chunk)
    auto load_stage = [&](int st, int k0) {
        const uint32_t a_base = As_u + (uint32_t)st * A_STAGE_F * 4;
        const uint32_t b_base = Bs_u + (uint32_t)st * B_STAGE_F * 4;
        #pragma unroll
        for (int i = 0; i < 4; i++) {
            int c = tid + i * 256;
            int r = c >> 3, kc = c & 7;
            // A: clamp ragged tail rows to T-1 (results masked at store)
            int gr = row0 + r; if (gr > T - 1) gr = T - 1;
            cp_async16(a_base + (uint32_t)(r * LDA + kc * 4) * 4,
                       x + (size_t)gr * DK + k0 + kc * 4);
            cp_async16(b_base + (uint32_t)(r * LDA + kc * 4) * 4,
                       w + (size_t)(e * DN + n0 + r) * DK + k0 + kc * 4);
        }
    };

    float acc[MITER][NITER][4];
    #pragma unroll
    for (int mi = 0; mi < MITER; mi++)
        #pragma unroll
        for (int ni = 0; ni < NITER; ni++)
            #pragma unroll
            for (int j = 0; j < 4; j++) acc[mi][ni][j] = 0.0f;

    // ---- prologue: prefetch STAGES-1 stages ----
    #pragma unroll
    for (int s = 0; s < STAGES - 1; s++) {
        load_stage(s, s * BK);
        cp_commit();
    }

    const int fr = lane >> 2;   // fragment row quad
    const int fc = lane & 3;    // fragment col

    for (int ks = 0; ks < NK; ks++) {
        cp_wait1();
        __syncthreads();

        // issue next load before compute (overlap copy with math)
        int nxt = ks + STAGES - 1;
        if (nxt < NK) load_stage(nxt % STAGES, nxt * BK);
        cp_commit();   // commit (possibly empty) to keep group counting uniform

        const int st = ks % STAGES;
        const float* Ast = As + st * A_STAGE_F;
        const float* Bst = Bs + st * B_STAGE_F;

        #pragma unroll
        for (int kk = 0; kk < BK / 8; kk++) {
            const int k = kk * 8;
            // A fragments: a0 (r,c) a1 (r+8,c) a2 (r,c+4) a3 (r+8,c+4)
            uint32_t af[MITER][4];
            #pragma unroll
            for (int mi = 0; mi < MITER; mi++) {
                const float* ap = Ast + (warp_m * WARP_M + mi * 16 + fr) * LDA + k + fc;
                af[mi][0] = rna_tf32_u(__float_as_uint(ap[0]));
                af[mi][1] = rna_tf32_u(__float_as_uint(ap[8 * LDA]));
                af[mi][2] = rna_tf32_u(__float_as_uint(ap[4]));
                af[mi][3] = rna_tf32_u(__float_as_uint(ap[8 * LDA + 4]));
            }
            // B fragments (col-major k x n): b0 (k=fc, n=fr), b1 (k=fc+4, n=fr)
            uint32_t bf[NITER][2];
            #pragma unroll
            for (int ni = 0; ni < NITER; ni++) {
                const float* bp = Bst + (warp_n * WARP_N + ni * 8 + fr) * LDA + k + fc;
                bf[ni][0] = rna_tf32_u(__float_as_uint(bp[0]));
                bf[ni][1] = rna_tf32_u(__float_as_uint(bp[4]));
            }
            #pragma unroll
            for (int mi = 0; mi < MITER; mi++)
                #pragma unroll
                for (int ni = 0; ni < NITER; ni++)
                    mma_tf32(acc[mi][ni][0], acc[mi][ni][1], acc[mi][ni][2], acc[mi][ni][3],
                             af[mi][0], af[mi][1], af[mi][2], af[mi][3],
                             bf[ni][0], bf[ni][1]);
        }
        __syncthreads();
    }

    // ---- epilogue: bias add + masked store ----
    #pragma unroll
    for (int mi = 0; mi < MITER; mi++) {
        const int r_lo = warp_m * WARP_M + mi * 16 + fr;
        const int r_hi = r_lo + 8;
        #pragma unroll
        for (int ni = 0; ni < NITER; ni++) {
            const int cn = warp_n * WARP_N + ni * 8 + 2 * fc;
            const float b0 = bias_s[cn], b1 = bias_s[cn + 1];
            if (r_lo < rows) {
                float2 v = {acc[mi][ni][0] + b0, acc[mi][ni][1] + b1};
                *reinterpret_cast<float2*>(out + (size_t)(row0 + r_lo) * DN + n0 + cn) = v;
            }
            if (r_hi < rows) {
                float2 v = {acc[mi][ni][2] + b0, acc[mi][ni][3] + b1};
                *reinterpret_cast<float2*>(out + (size_t)(row0 + r_hi) * DN + n0 + cn) = v;
            }
        }
    }
}

// ---------------- host ----------------
extern "C" void kernel_launch(void* const* d_in, const int* in_sizes, int n_in,
                              void* d_out, int out_size) {
    const float* x    = (const float*)d_in[0];
    const void*  freq = d_in[1];
    const float* w    = (const float*)d_in[2];
    const float* bias = (const float*)d_in[3];
    float* out = (float*)d_out;
    const int T = in_sizes[0] / DK;

    meta_kernel<<<1, 1>>>(freq, T);

    cudaFuncSetAttribute(gemm_kernel, cudaFuncAttributeMaxDynamicSharedMemorySize, SMEM_BYTES);
    dim3 grid(DN / BN, MAX_TILES);
    gemm_kernel<<<grid, 256, SMEM_BYTES>>>(x, w, bias, out, T);
    (void)n_in; (void)out_size;
}

// round 7
// speedup vs baseline: 1.0898x; 1.0898x over previous
#include <cuda_runtime.h>
#include <cstdint>

// ---------------- problem constants ----------------
#define DK 1024
#define DN 1024
#define NEXP 32
#define MAX_TILES 1056

// ---------------- GEMM tiling ----------------
#define BM 128
#define BN 256
#define BK 32
#define STAGES 3
#define NK (DK / BK)        // 32 k-stages
#define PAD 4
#define LDA (BK + PAD)      // 36 floats/row -> conflict-free frag loads
#define A_STAGE_F (BM * LDA)    // 4608
#define B_STAGE_F (BN * LDA)    // 9216
#define SMEM_FLOATS (STAGES * (A_STAGE_F + B_STAGE_F) + BN)
#define SMEM_BYTES (SMEM_FLOATS * 4)    // 166,912 B

// warp layout: 8 warps = 2 (M) x 4 (N); warp tile 64x64
#define WARP_M 64
#define WARP_N 64
#define MITER (WARP_M / 16)   // 4
#define NITER (WARP_N / 8)    // 8

// ---------------- device scratch ----------------
__device__ int   g_tile_expert[MAX_TILES];
__device__ int   g_tile_row0[MAX_TILES];
__device__ int   g_tile_rows[MAX_TILES];
__device__ int   g_num_tiles;
__device__ float g_wr[(size_t)NEXP * DN * DK];   // tf32(RNA)-rounded weights

// ---------------- helpers ----------------
__device__ __forceinline__ uint32_t smem_u32(const void* p) {
    uint32_t a;
    asm("{ .reg .u64 t; cvta.to.shared.u64 t, %1; cvt.u32.u64 %0, t; }" : "=r"(a) : "l"(p));
    return a;
}
__device__ __forceinline__ void cp_async16(uint32_t dst, const void* src) {
    asm volatile("cp.async.cg.shared.global [%0], [%1], 16;" :: "r"(dst), "l"(src) : "memory");
}
__device__ __forceinline__ void cp_commit() {
    asm volatile("cp.async.commit_group;" ::: "memory");
}
__device__ __forceinline__ void cp_wait1() {
    asm volatile("cp.async.wait_group 1;" ::: "memory");
}
__device__ __forceinline__ float rna_tf32(float f) {
    uint32_t u = __float_as_uint(f), r;
    asm("cvt.rna.tf32.f32 %0, %1;" : "=r"(r) : "r"(u));
    return __uint_as_float(r);
}
__device__ __forceinline__ void mma_tf32(float& c0, float& c1, float& c2, float& c3,
                                         uint32_t a0, uint32_t a1, uint32_t a2, uint32_t a3,
                                         uint32_t b0, uint32_t b1) {
    asm volatile(
        "mma.sync.aligned.m16n8k8.row.col.f32.tf32.tf32.f32 "
        "{%0,%1,%2,%3}, {%4,%5,%6,%7}, {%8,%9}, {%0,%1,%2,%3};"
        : "+f"(c0), "+f"(c1), "+f"(c2), "+f"(c3)
        : "r"(a0), "r"(a1), "r"(a2), "r"(a3), "r"(b0), "r"(b1));
}

// ---------------- kernel 1: tile metadata ----------------
__global__ void meta_kernel(const void* __restrict__ freqv, int T) {
    if (threadIdx.x != 0 || blockIdx.x != 0) return;
    const int* f32p = (const int*)freqv;
    const long long* f64p = (const long long*)freqv;
    long long s32 = 0;
    for (int i = 0; i < NEXP; i++) s32 += f32p[i];
    const bool is64 = (s32 != (long long)T);
    int nt = 0, off = 0;
    for (int e = 0; e < NEXP; e++) {
        int c = is64 ? (int)f64p[e] : f32p[e];
        for (int r = 0; r < c; r += BM) {
            g_tile_expert[nt] = e;
            g_tile_row0[nt] = off + r;
            g_tile_rows[nt] = (c - r < BM) ? (c - r) : BM;
            nt++;
        }
        off += c;
    }
    g_num_tiles = nt;
}

// ---------------- kernel 2: weights fp32 -> tf32 (RNA, unbiased) ----------------
__global__ void round_w_kernel(const float4* __restrict__ w) {
    const int n4 = NEXP * DN * (DK / 4);
    float4* dst = reinterpret_cast<float4*>(g_wr);
    for (int i = blockIdx.x * blockDim.x + threadIdx.x; i < n4; i += gridDim.x * blockDim.x) {
        float4 v = w[i];
        v.x = rna_tf32(v.x); v.y = rna_tf32(v.y);
        v.z = rna_tf32(v.z); v.w = rna_tf32(v.w);
        dst[i] = v;
    }
}

// ---------------- kernel 3: grouped GEMM (tf32 mma.sync, 128x256 CTA) ----------
__global__ void __launch_bounds__(256, 1) gemm_kernel(
    const float* __restrict__ x,      // [T, DK]  (truncated to tf32 by HMMA)
    const float* __restrict__ bias,   // [NEXP, DN]
    float* __restrict__ out,          // [T, DN]
    int T)
{
    extern __shared__ float smem[];
    float* As = smem;                               // [STAGES][BM][LDA]
    float* Bs = smem + STAGES * A_STAGE_F;          // [STAGES][BN][LDA]
    float* bias_s = Bs + STAGES * B_STAGE_F;        // [BN]

    const int tile = blockIdx.y;
    if (tile >= g_num_tiles) return;

    const int n0 = blockIdx.x * BN;
    const int e = g_tile_expert[tile];
    const int row0 = g_tile_row0[tile];
    const int rows = g_tile_rows[tile];

    const int tid = threadIdx.x;
    const int lane = tid & 31;
    const int wid = tid >> 5;
    const int warp_m = wid & 1;        // 0..1
    const int warp_n = wid >> 1;       // 0..3

    const uint32_t As_u = smem_u32(As);
    const uint32_t Bs_u = smem_u32(Bs);
    const float* __restrict__ wr = g_wr;

    bias_s[tid] = bias[e * DN + n0 + tid];

    // ---- stage loader: A 1024 chunks (4/thread), B 2048 chunks (8/thread) ----
    auto load_stage = [&](int st, int k0) {
        const uint32_t a_base = As_u + (uint32_t)st * A_STAGE_F * 4;
        const uint32_t b_base = Bs_u + (uint32_t)st * B_STAGE_F * 4;
        #pragma unroll
        for (int i = 0; i < 4; i++) {
            int c = tid + i * 256;
            int r = c >> 3, kc = c & 7;
            int gr = row0 + r; if (gr > T - 1) gr = T - 1;   // ragged tail clamp
            cp_async16(a_base + (uint32_t)(r * LDA + kc * 4) * 4,
                       x + (size_t)gr * DK + k0 + kc * 4);
        }
        #pragma unroll
        for (int i = 0; i < 8; i++) {
            int c = tid + i * 256;
            int r = c >> 3, kc = c & 7;
            cp_async16(b_base + (uint32_t)(r * LDA + kc * 4) * 4,
                       wr + (size_t)(e * DN + n0 + r) * DK + k0 + kc * 4);
        }
    };

    float acc[MITER][NITER][4];
    #pragma unroll
    for (int mi = 0; mi < MITER; mi++)
        #pragma unroll
        for (int ni = 0; ni < NITER; ni++)
            #pragma unroll
            for (int j = 0; j < 4; j++) acc[mi][ni][j] = 0.0f;

    #pragma unroll
    for (int s = 0; s < STAGES - 1; s++) {
        load_stage(s, s * BK);
        cp_commit();
    }

    const int fr = lane >> 2;   // 0..7
    const int fc = lane & 3;    // 0..3

    for (int ks = 0; ks < NK; ks++) {
        cp_wait1();
        __syncthreads();

        int nxt = ks + STAGES - 1;
        if (nxt < NK) load_stage(nxt % STAGES, nxt * BK);
        cp_commit();

        const int st = ks % STAGES;
        const float* Ast = As + st * A_STAGE_F;
        const float* Bst = Bs + st * B_STAGE_F;

        #pragma unroll
        for (int kk = 0; kk < BK / 8; kk++) {
            const int k = kk * 8;
            uint32_t af[MITER][4];
            #pragma unroll
            for (int mi = 0; mi < MITER; mi++) {
                const float* ap = Ast + (warp_m * WARP_M + mi * 16 + fr) * LDA + k + fc;
                af[mi][0] = __float_as_uint(ap[0]);
                af[mi][1] = __float_as_uint(ap[8 * LDA]);
                af[mi][2] = __float_as_uint(ap[4]);
                af[mi][3] = __float_as_uint(ap[8 * LDA + 4]);
            }
            uint32_t bf[NITER][2];
            #pragma unroll
            for (int ni = 0; ni < NITER; ni++) {
                const float* bp = Bst + (warp_n * WARP_N + ni * 8 + fr) * LDA + k + fc;
                bf[ni][0] = __float_as_uint(bp[0]);
                bf[ni][1] = __float_as_uint(bp[4]);
            }
            #pragma unroll
            for (int mi = 0; mi < MITER; mi++)
                #pragma unroll
                for (int ni = 0; ni < NITER; ni++)
                    mma_tf32(acc[mi][ni][0], acc[mi][ni][1], acc[mi][ni][2], acc[mi][ni][3],
                             af[mi][0], af[mi][1], af[mi][2], af[mi][3],
                             bf[ni][0], bf[ni][1]);
        }
        __syncthreads();
    }

    // ---- epilogue: bias add + masked store ----
    #pragma unroll
    for (int mi = 0; mi < MITER; mi++) {
        const int r_lo = warp_m * WARP_M + mi * 16 + fr;
        const int r_hi = r_lo + 8;
        #pragma unroll
        for (int ni = 0; ni < NITER; ni++) {
            const int cn = warp_n * WARP_N + ni * 8 + 2 * fc;
            const float b0 = bias_s[cn], b1 = bias_s[cn + 1];
            if (r_lo < rows) {
                float2 v = {acc[mi][ni][0] + b0, acc[mi][ni][1] + b1};
                *reinterpret_cast<float2*>(out + (size_t)(row0 + r_lo) * DN + n0 + cn) = v;
            }
            if (r_hi < rows) {
                float2 v = {acc[mi][ni][2] + b0, acc[mi][ni][3] + b1};
                *reinterpret_cast<float2*>(out + (size_t)(row0 + r_hi) * DN + n0 + cn) = v;
            }
        }
    }
}

// ---------------- host ----------------
extern "C" void kernel_launch(void* const* d_in, const int* in_sizes, int n_in,
                              void* d_out, int out_size) {
    const float* x    = (const float*)d_in[0];
    const void*  freq = d_in[1];
    const float* w    = (const float*)d_in[2];
    const float* bias = (const float*)d_in[3];
    float* out = (float*)d_out;
    const int T = in_sizes[0] / DK;

    meta_kernel<<<1, 1>>>(freq, T);
    round_w_kernel<<<2048, 256>>>(reinterpret_cast<const float4*>(w));

    cudaFuncSetAttribute(gemm_kernel, cudaFuncAttributeMaxDynamicSharedMemorySize, SMEM_BYTES);
    dim3 grid(DN / BN, MAX_TILES);
    gemm_kernel<<<grid, 256, SMEM_BYTES>>>(x, bias, out, T);
    (void)n_in; (void)out_size;
}

// round 8
// speedup vs baseline: 1.1119x; 1.0203x over previous
#include <cuda_runtime.h>
#include <cstdint>

// ---------------- problem constants ----------------
#define DK 1024
#define DN 1024
#define NEXP 32
#define MAX_TILES 1056

// ---------------- GEMM tiling ----------------
#define BM 128
#define BN 256
#define BK 32
#define STAGES 3
#define NK (DK / BK)        // 32 k-stages
#define PAD 4
#define LDA (BK + PAD)      // 36 floats/row; 144B row stride -> conflict-free LDSM
#define A_STAGE_F (BM * LDA)    // 4608
#define B_STAGE_F (BN * LDA)    // 9216
#define SMEM_FLOATS (STAGES * (A_STAGE_F + B_STAGE_F) + BN)
#define SMEM_BYTES (SMEM_FLOATS * 4)    // 166,912 B

// warp layout: 8 warps = 2 (M) x 4 (N); warp tile 64x64
#define WARP_M 64
#define WARP_N 64
#define MITER (WARP_M / 16)   // 4
#define NITER (WARP_N / 8)    // 8

// ---------------- device scratch ----------------
__device__ int   g_tile_expert[MAX_TILES];
__device__ int   g_tile_row0[MAX_TILES];
__device__ int   g_tile_rows[MAX_TILES];
__device__ int   g_num_tiles;
__device__ float g_wr[(size_t)NEXP * DN * DK];   // tf32(RNA)-rounded weights

// ---------------- helpers ----------------
__device__ __forceinline__ uint32_t smem_u32(const void* p) {
    uint32_t a;
    asm("{ .reg .u64 t; cvta.to.shared.u64 t, %1; cvt.u32.u64 %0, t; }" : "=r"(a) : "l"(p));
    return a;
}
__device__ __forceinline__ void cp_async16(uint32_t dst, const void* src) {
    asm volatile("cp.async.cg.shared.global [%0], [%1], 16;" :: "r"(dst), "l"(src) : "memory");
}
__device__ __forceinline__ void cp_commit() {
    asm volatile("cp.async.commit_group;" ::: "memory");
}
__device__ __forceinline__ void cp_wait1() {
    asm volatile("cp.async.wait_group 1;" ::: "memory");
}
__device__ __forceinline__ float rna_tf32(float f) {
    uint32_t u = __float_as_uint(f), r;
    asm("cvt.rna.tf32.f32 %0, %1;" : "=r"(r) : "r"(u));
    return __uint_as_float(r);
}
__device__ __forceinline__ void ldsm_x4(uint32_t& r0, uint32_t& r1, uint32_t& r2, uint32_t& r3,
                                        uint32_t addr) {
    asm volatile("ldmatrix.sync.aligned.m8n8.x4.shared.b16 {%0,%1,%2,%3}, [%4];"
        : "=r"(r0), "=r"(r1), "=r"(r2), "=r"(r3) : "r"(addr));
}
__device__ __forceinline__ void mma_tf32(float& c0, float& c1, float& c2, float& c3,
                                         uint32_t a0, uint32_t a1, uint32_t a2, uint32_t a3,
                                         uint32_t b0, uint32_t b1) {
    asm volatile(
        "mma.sync.aligned.m16n8k8.row.col.f32.tf32.tf32.f32 "
        "{%0,%1,%2,%3}, {%4,%5,%6,%7}, {%8,%9}, {%0,%1,%2,%3};"
        : "+f"(c0), "+f"(c1), "+f"(c2), "+f"(c3)
        : "r"(a0), "r"(a1), "r"(a2), "r"(a3), "r"(b0), "r"(b1));
}

// ---------------- kernel 1: tile metadata ----------------
__global__ void meta_kernel(const void* __restrict__ freqv, int T) {
    if (threadIdx.x != 0 || blockIdx.x != 0) return;
    const int* f32p = (const int*)freqv;
    const long long* f64p = (const long long*)freqv;
    long long s32 = 0;
    for (int i = 0; i < NEXP; i++) s32 += f32p[i];
    const bool is64 = (s32 != (long long)T);
    int nt = 0, off = 0;
    for (int e = 0; e < NEXP; e++) {
        int c = is64 ? (int)f64p[e] : f32p[e];
        for (int r = 0; r < c; r += BM) {
            g_tile_expert[nt] = e;
            g_tile_row0[nt] = off + r;
            g_tile_rows[nt] = (c - r < BM) ? (c - r) : BM;
            nt++;
        }
        off += c;
    }
    g_num_tiles = nt;
}

// ---------------- kernel 2: weights fp32 -> tf32 (RNA, unbiased) ----------------
__global__ void round_w_kernel(const float4* __restrict__ w) {
    const int n4 = NEXP * DN * (DK / 4);
    float4* dst = reinterpret_cast<float4*>(g_wr);
    for (int i = blockIdx.x * blockDim.x + threadIdx.x; i < n4; i += gridDim.x * blockDim.x) {
        float4 v = w[i];
        v.x = rna_tf32(v.x); v.y = rna_tf32(v.y);
        v.z = rna_tf32(v.z); v.w = rna_tf32(v.w);
        dst[i] = v;
    }
}

// ---------------- kernel 3: grouped GEMM (tf32 mma.sync + ldmatrix) ----------
__global__ void __launch_bounds__(256, 1) gemm_kernel(
    const float* __restrict__ x,      // [T, DK]  (truncated to tf32 by HMMA)
    const float* __restrict__ bias,   // [NEXP, DN]
    float* __restrict__ out,          // [T, DN]
    int T)
{
    extern __shared__ float smem[];
    float* As = smem;                               // [STAGES][BM][LDA]
    float* Bs = smem + STAGES * A_STAGE_F;          // [STAGES][BN][LDA]
    float* bias_s = Bs + STAGES * B_STAGE_F;        // [BN]

    const int tile = blockIdx.y;
    if (tile >= g_num_tiles) return;

    const int n0 = blockIdx.x * BN;
    const int e = g_tile_expert[tile];
    const int row0 = g_tile_row0[tile];
    const int rows = g_tile_rows[tile];

    const int tid = threadIdx.x;
    const int lane = tid & 31;
    const int wid = tid >> 5;
    const int warp_m = wid & 1;        // 0..1
    const int warp_n = wid >> 1;       // 0..3

    const uint32_t As_u = smem_u32(As);
    const uint32_t Bs_u = smem_u32(Bs);
    const float* __restrict__ wr = g_wr;

    bias_s[tid] = bias[e * DN + n0 + tid];

    // ldmatrix per-lane address offsets (bytes, relative to stage base)
    // A x4: matrices [rows0-7,k0-3][rows8-15,k0-3][rows0-7,k4-7][rows8-15,k4-7]
    const uint32_t a_lane_off =
        (uint32_t)(((warp_m * WARP_M + (lane & 15)) * LDA + (lane >> 4) * 4) * 4);
    // B x4: [n0-7,k0-3][n0-7,k4-7][n8-15,k0-3][n8-15,k4-7]
    const uint32_t b_lane_off =
        (uint32_t)(((warp_n * WARP_N + ((lane & 7) | ((lane >> 4) << 3))) * LDA
                    + ((lane >> 3) & 1) * 4) * 4);

    // ---- stage loader: A 1024 chunks (4/thread), B 2048 chunks (8/thread) ----
    auto load_stage = [&](int st, int k0) {
        const uint32_t a_base = As_u + (uint32_t)st * A_STAGE_F * 4;
        const uint32_t b_base = Bs_u + (uint32_t)st * B_STAGE_F * 4;
        #pragma unroll
        for (int i = 0; i < 4; i++) {
            int c = tid + i * 256;
            int r = c >> 3, kc = c & 7;
            int gr = row0 + r; if (gr > T - 1) gr = T - 1;   // ragged tail clamp
            cp_async16(a_base + (uint32_t)(r * LDA + kc * 4) * 4,
                       x + (size_t)gr * DK + k0 + kc * 4);
        }
        #pragma unroll
        for (int i = 0; i < 8; i++) {
            int c = tid + i * 256;
            int r = c >> 3, kc = c & 7;
            cp_async16(b_base + (uint32_t)(r * LDA + kc * 4) * 4,
                       wr + (size_t)(e * DN + n0 + r) * DK + k0 + kc * 4);
        }
    };

    float acc[MITER][NITER][4];
    #pragma unroll
    for (int mi = 0; mi < MITER; mi++)
        #pragma unroll
        for (int ni = 0; ni < NITER; ni++)
            #pragma unroll
            for (int j = 0; j < 4; j++) acc[mi][ni][j] = 0.0f;

    #pragma unroll
    for (int s = 0; s < STAGES - 1; s++) {
        load_stage(s, s * BK);
        cp_commit();
    }

    uint32_t af[2][MITER][4];
    uint32_t bf[2][NITER][2];

    for (int ks = 0; ks < NK; ks++) {
        cp_wait1();
        __syncthreads();

        int nxt = ks + STAGES - 1;
        if (nxt < NK) load_stage(nxt % STAGES, nxt * BK);
        cp_commit();

        const int st = ks % STAGES;
        const uint32_t AstU = As_u + (uint32_t)st * A_STAGE_F * 4;
        const uint32_t BstU = Bs_u + (uint32_t)st * B_STAGE_F * 4;

        // load fragments for kk=0
        #pragma unroll
        for (int mi = 0; mi < MITER; mi++)
            ldsm_x4(af[0][mi][0], af[0][mi][1], af[0][mi][2], af[0][mi][3],
                    AstU + a_lane_off + (uint32_t)(mi * 16 * LDA) * 4);
        #pragma unroll
        for (int p = 0; p < NITER / 2; p++)
            ldsm_x4(bf[0][2 * p][0], bf[0][2 * p][1], bf[0][2 * p + 1][0], bf[0][2 * p + 1][1],
                    BstU + b_lane_off + (uint32_t)(p * 16 * LDA) * 4);

        #pragma unroll
        for (int kk = 0; kk < BK / 8; kk++) {
            const int cur = kk & 1;
            if (kk < BK / 8 - 1) {
                const int k = (kk + 1) * 8;
                #pragma unroll
                for (int mi = 0; mi < MITER; mi++)
                    ldsm_x4(af[cur ^ 1][mi][0], af[cur ^ 1][mi][1],
                            af[cur ^ 1][mi][2], af[cur ^ 1][mi][3],
                            AstU + a_lane_off + (uint32_t)(mi * 16 * LDA + k) * 4);
                #pragma unroll
                for (int p = 0; p < NITER / 2; p++)
                    ldsm_x4(bf[cur ^ 1][2 * p][0], bf[cur ^ 1][2 * p][1],
                            bf[cur ^ 1][2 * p + 1][0], bf[cur ^ 1][2 * p + 1][1],
                            BstU + b_lane_off + (uint32_t)(p * 16 * LDA + k) * 4);
            }
            #pragma unroll
            for (int mi = 0; mi < MITER; mi++)
                #pragma unroll
                for (int ni = 0; ni < NITER; ni++)
                    mma_tf32(acc[mi][ni][0], acc[mi][ni][1], acc[mi][ni][2], acc[mi][ni][3],
                             af[cur][mi][0], af[cur][mi][1], af[cur][mi][2], af[cur][mi][3],
                             bf[cur][ni][0], bf[cur][ni][1]);
        }
        __syncthreads();
    }

    // ---- epilogue: bias add + masked store ----
    const int fr = lane >> 2;
    const int fc = lane & 3;
    #pragma unroll
    for (int mi = 0; mi < MITER; mi++) {
        const int r_lo = warp_m * WARP_M + mi * 16 + fr;
        const int r_hi = r_lo + 8;
        #pragma unroll
        for (int ni = 0; ni < NITER; ni++) {
            const int cn = warp_n * WARP_N + ni * 8 + 2 * fc;
            const float b0 = bias_s[cn], b1 = bias_s[cn + 1];
            if (r_lo < rows) {
                float2 v = {acc[mi][ni][0] + b0, acc[mi][ni][1] + b1};
                *reinterpret_cast<float2*>(out + (size_t)(row0 + r_lo) * DN + n0 + cn) = v;
            }
            if (r_hi < rows) {
                float2 v = {acc[mi][ni][2] + b0, acc[mi][ni][3] + b1};
                *reinterpret_cast<float2*>(out + (size_t)(row0 + r_hi) * DN + n0 + cn) = v;
            }
        }
    }
}

// ---------------- host ----------------
extern "C" void kernel_launch(void* const* d_in, const int* in_sizes, int n_in,
                              void* d_out, int out_size) {
    const float* x    = (const float*)d_in[0];
    const void*  freq = d_in[1];
    const float* w    = (const float*)d_in[2];
    const float* bias = (const float*)d_in[3];
    float* out = (float*)d_out;
    const int T = in_sizes[0] / DK;

    meta_kernel<<<1, 1>>>(freq, T);
    round_w_kernel<<<2048, 256>>>(reinterpret_cast<const float4*>(w));

    cudaFuncSetAttribute(gemm_kernel, cudaFuncAttributeMaxDynamicSharedMemorySize, SMEM_BYTES);
    dim3 grid(DN / BN, MAX_TILES);
    gemm_kernel<<<grid, 256, SMEM_BYTES>>>(x, bias, out, T);
    (void)n_in; (void)out_size;
}

// round 9
// speedup vs baseline: 1.1443x; 1.0291x over previous
#include <cuda_runtime.h>
#include <cstdint>

// ---------------- problem constants ----------------
#define DK 1024
#define DN 1024
#define NEXP 32
#define MAX_TILES 1056

// ---------------- GEMM tiling ----------------
#define BM 128
#define BN 256
#define BK 32
#define STAGES 3
#define NK (DK / BK)        // 32 k-stages
#define PAD 4
#define LDA (BK + PAD)      // 36 floats/row; 144B stride -> conflict-free LDSM
#define A_STAGE_F (BM * LDA)    // 4608
#define B_STAGE_F (BN * LDA)    // 9216
#define SMEM_FLOATS (STAGES * (A_STAGE_F + B_STAGE_F) + BN)
#define SMEM_BYTES (SMEM_FLOATS * 4)    // 166,912 B

// warp layout: 16 warps = 2 (M) x 8 (N); warp tile 64x32
#define NTHREADS 512
#define WARP_M 64
#define WARP_N 32
#define MITER (WARP_M / 16)   // 4
#define NITER (WARP_N / 8)    // 4

// ---------------- device scratch ----------------
__device__ int   g_tile_expert[MAX_TILES];
__device__ int   g_tile_row0[MAX_TILES];
__device__ int   g_tile_rows[MAX_TILES];
__device__ int   g_num_tiles;
__device__ float g_wr[(size_t)NEXP * DN * DK];   // tf32(RNA)-rounded weights

// ---------------- helpers ----------------
__device__ __forceinline__ uint32_t smem_u32(const void* p) {
    uint32_t a;
    asm("{ .reg .u64 t; cvta.to.shared.u64 t, %1; cvt.u32.u64 %0, t; }" : "=r"(a) : "l"(p));
    return a;
}
__device__ __forceinline__ void cp_async16(uint32_t dst, const void* src) {
    asm volatile("cp.async.cg.shared.global [%0], [%1], 16;" :: "r"(dst), "l"(src) : "memory");
}
__device__ __forceinline__ void cp_commit() {
    asm volatile("cp.async.commit_group;" ::: "memory");
}
__device__ __forceinline__ void cp_wait1() {
    asm volatile("cp.async.wait_group 1;" ::: "memory");
}
__device__ __forceinline__ float rna_tf32(float f) {
    uint32_t u = __float_as_uint(f), r;
    asm("cvt.rna.tf32.f32 %0, %1;" : "=r"(r) : "r"(u));
    return __uint_as_float(r);
}
__device__ __forceinline__ void ldsm_x4(uint32_t& r0, uint32_t& r1, uint32_t& r2, uint32_t& r3,
                                        uint32_t addr) {
    asm volatile("ldmatrix.sync.aligned.m8n8.x4.shared.b16 {%0,%1,%2,%3}, [%4];"
        : "=r"(r0), "=r"(r1), "=r"(r2), "=r"(r3) : "r"(addr));
}
__device__ __forceinline__ void mma_tf32(float& c0, float& c1, float& c2, float& c3,
                                         uint32_t a0, uint32_t a1, uint32_t a2, uint32_t a3,
                                         uint32_t b0, uint32_t b1) {
    asm volatile(
        "mma.sync.aligned.m16n8k8.row.col.f32.tf32.tf32.f32 "
        "{%0,%1,%2,%3}, {%4,%5,%6,%7}, {%8,%9}, {%0,%1,%2,%3};"
        : "+f"(c0), "+f"(c1), "+f"(c2), "+f"(c3)
        : "r"(a0), "r"(a1), "r"(a2), "r"(a3), "r"(b0), "r"(b1));
}

// ---------------- kernel 1: tile metadata ----------------
__global__ void meta_kernel(const void* __restrict__ freqv, int T) {
    if (threadIdx.x != 0 || blockIdx.x != 0) return;
    const int* f32p = (const int*)freqv;
    const long long* f64p = (const long long*)freqv;
    long long s32 = 0;
    for (int i = 0; i < NEXP; i++) s32 += f32p[i];
    const bool is64 = (s32 != (long long)T);
    int nt = 0, off = 0;
    for (int e = 0; e < NEXP; e++) {
        int c = is64 ? (int)f64p[e] : f32p[e];
        for (int r = 0; r < c; r += BM) {
            g_tile_expert[nt] = e;
            g_tile_row0[nt] = off + r;
            g_tile_rows[nt] = (c - r < BM) ? (c - r) : BM;
            nt++;
        }
        off += c;
    }
    g_num_tiles = nt;
}

// ---------------- kernel 2: weights fp32 -> tf32 (RNA, unbiased) ----------------
__global__ void round_w_kernel(const float4* __restrict__ w) {
    const int n4 = NEXP * DN * (DK / 4);
    float4* dst = reinterpret_cast<float4*>(g_wr);
    for (int i = blockIdx.x * blockDim.x + threadIdx.x; i < n4; i += gridDim.x * blockDim.x) {
        float4 v = w[i];
        v.x = rna_tf32(v.x); v.y = rna_tf32(v.y);
        v.z = rna_tf32(v.z); v.w = rna_tf32(v.w);
        dst[i] = v;
    }
}

// ---------------- kernel 3: grouped GEMM (tf32 mma.sync, 512 threads) ----------
__global__ void __launch_bounds__(NTHREADS, 1) gemm_kernel(
    const float* __restrict__ x,      // [T, DK]  (truncated to tf32 by HMMA)
    const float* __restrict__ bias,   // [NEXP, DN]
    float* __restrict__ out,          // [T, DN]
    int T)
{
    extern __shared__ float smem[];
    float* As = smem;                               // [STAGES][BM][LDA]
    float* Bs = smem + STAGES * A_STAGE_F;          // [STAGES][BN][LDA]
    float* bias_s = Bs + STAGES * B_STAGE_F;        // [BN]

    const int tile = blockIdx.y;
    if (tile >= g_num_tiles) return;

    const int n0 = blockIdx.x * BN;
    const int e = g_tile_expert[tile];
    const int row0 = g_tile_row0[tile];
    const int rows = g_tile_rows[tile];

    const int tid = threadIdx.x;
    const int lane = tid & 31;
    const int wid = tid >> 5;
    const int warp_m = wid & 1;        // 0..1
    const int warp_n = wid >> 1;       // 0..7

    const uint32_t As_u = smem_u32(As);
    const uint32_t Bs_u = smem_u32(Bs);
    const float* __restrict__ wr = g_wr;

    if (tid < BN) bias_s[tid] = bias[e * DN + n0 + tid];

    // ldmatrix per-lane byte offsets (relative to stage base)
    // A x4: [r0-7,k0-3][r8-15,k0-3][r0-7,k4-7][r8-15,k4-7]
    const uint32_t a_lane_off =
        (uint32_t)(((warp_m * WARP_M + (lane & 15)) * LDA + (lane >> 4) * 4) * 4);
    // B x4: [n0-7,k0-3][n0-7,k4-7][n8-15,k0-3][n8-15,k4-7]
    const uint32_t b_lane_off =
        (uint32_t)(((warp_n * WARP_N + ((lane & 7) | ((lane >> 4) << 3))) * LDA
                    + ((lane >> 3) & 1) * 4) * 4);

    // ---- stage loader: A 1024 chunks (2/thread), B 2048 chunks (4/thread) ----
    auto load_stage = [&](int st, int k0) {
        const uint32_t a_base = As_u + (uint32_t)st * A_STAGE_F * 4;
        const uint32_t b_base = Bs_u + (uint32_t)st * B_STAGE_F * 4;
        #pragma unroll
        for (int i = 0; i < 2; i++) {
            int c = tid + i * NTHREADS;
            int r = c >> 3, kc = c & 7;
            int gr = row0 + r; if (gr > T - 1) gr = T - 1;   // ragged tail clamp
            cp_async16(a_base + (uint32_t)(r * LDA + kc * 4) * 4,
                       x + (size_t)gr * DK + k0 + kc * 4);
        }
        #pragma unroll
        for (int i = 0; i < 4; i++) {
            int c = tid + i * NTHREADS;
            int r = c >> 3, kc = c & 7;
            cp_async16(b_base + (uint32_t)(r * LDA + kc * 4) * 4,
                       wr + (size_t)(e * DN + n0 + r) * DK + k0 + kc * 4);
        }
    };

    float acc[MITER][NITER][4];
    #pragma unroll
    for (int mi = 0; mi < MITER; mi++)
        #pragma unroll
        for (int ni = 0; ni < NITER; ni++)
            #pragma unroll
            for (int j = 0; j < 4; j++) acc[mi][ni][j] = 0.0f;

    #pragma unroll
    for (int s = 0; s < STAGES - 1; s++) {
        load_stage(s, s * BK);
        cp_commit();
    }

    for (int ks = 0; ks < NK; ks++) {
        cp_wait1();
        __syncthreads();

        int nxt = ks + STAGES - 1;
        if (nxt < NK) load_stage(nxt % STAGES, nxt * BK);
        cp_commit();

        const int st = ks % STAGES;
        const uint32_t AstU = As_u + (uint32_t)st * A_STAGE_F * 4;
        const uint32_t BstU = Bs_u + (uint32_t)st * B_STAGE_F * 4;

        #pragma unroll
        for (int kk = 0; kk < BK / 8; kk++) {
            const int k = kk * 8;
            uint32_t af[MITER][4];
            #pragma unroll
            for (int mi = 0; mi < MITER; mi++)
                ldsm_x4(af[mi][0], af[mi][1], af[mi][2], af[mi][3],
                        AstU + a_lane_off + (uint32_t)(mi * 16 * LDA + k) * 4);
            uint32_t bf[NITER][2];
            #pragma unroll
            for (int p = 0; p < NITER / 2; p++)
                ldsm_x4(bf[2 * p][0], bf[2 * p][1], bf[2 * p + 1][0], bf[2 * p + 1][1],
                        BstU + b_lane_off + (uint32_t)(p * 16 * LDA + k) * 4);
            #pragma unroll
            for (int mi = 0; mi < MITER; mi++)
                #pragma unroll
                for (int ni = 0; ni < NITER; ni++)
                    mma_tf32(acc[mi][ni][0], acc[mi][ni][1], acc[mi][ni][2], acc[mi][ni][3],
                             af[mi][0], af[mi][1], af[mi][2], af[mi][3],
                             bf[ni][0], bf[ni][1]);
        }
        // no trailing __syncthreads: stage ks%STAGES is only overwritten by loads
        // issued after the NEXT iteration's leading __syncthreads.
    }

    // ---- epilogue: bias add + masked store ----
    const int fr = lane >> 2;
    const int fc = lane & 3;
    #pragma unroll
    for (int mi = 0; mi < MITER; mi++) {
        const int r_lo = warp_m * WARP_M + mi * 16 + fr;
        const int r_hi = r_lo + 8;
        #pragma unroll
        for (int ni = 0; ni < NITER; ni++) {
            const int cn = warp_n * WARP_N + ni * 8 + 2 * fc;
            const float b0 = bias_s[cn], b1 = bias_s[cn + 1];
            if (r_lo < rows) {
                float2 v = {acc[mi][ni][0] + b0, acc[mi][ni][1] + b1};
                *reinterpret_cast<float2*>(out + (size_t)(row0 + r_lo) * DN + n0 + cn) = v;
            }
            if (r_hi < rows) {
                float2 v = {acc[mi][ni][2] + b0, acc[mi][ni][3] + b1};
                *reinterpret_cast<float2*>(out + (size_t)(row0 + r_hi) * DN + n0 + cn) = v;
            }
        }
    }
}

// ---------------- host ----------------
extern "C" void kernel_launch(void* const* d_in, const int* in_sizes, int n_in,
                              void* d_out, int out_size) {
    const float* x    = (const float*)d_in[0];
    const void*  freq = d_in[1];
    const float* w    = (const float*)d_in[2];
    const float* bias = (const float*)d_in[3];
    float* out = (float*)d_out;
    const int T = in_sizes[0] / DK;

    meta_kernel<<<1, 1>>>(freq, T);
    round_w_kernel<<<2048, 256>>>(reinterpret_cast<const float4*>(w));

    cudaFuncSetAttribute(gemm_kernel, cudaFuncAttributeMaxDynamicSharedMemorySize, SMEM_BYTES);
    dim3 grid(DN / BN, MAX_TILES);
    gemm_kernel<<<grid, NTHREADS, SMEM_BYTES>>>(x, bias, out, T);
    (void)n_in; (void)out_size;
}

// round 10
// speedup vs baseline: 1.2434x; 1.0866x over previous
#include <cuda_runtime.h>
#include <cstdint>

// ---------------- problem constants ----------------
#define DK 1024
#define DN 1024
#define NEXP 32
#define MAX_TILES 1056

// ---------------- GEMM tiling ----------------
#define BM 128
#define BN 128
#define BK 32
#define STAGES 3
#define NK (DK / BK)        // 32 k-stages
#define PAD 4
#define LDA (BK + PAD)      // 36 floats/row; 144B stride -> conflict-free LDSM
#define A_STAGE_F (BM * LDA)    // 4608
#define B_STAGE_F (BN * LDA)    // 4608
#define SMEM_FLOATS (STAGES * (A_STAGE_F + B_STAGE_F) + BN)
#define SMEM_BYTES (SMEM_FLOATS * 4)    // 111,104 B  (x2 CTAs = 222,208 <= 228KB)

// warp layout: 8 warps = 2 (M) x 4 (N); warp tile 64x32; 2 CTAs/SM -> 4 warps/SMSP
#define NTHREADS 256
#define WARP_M 64
#define WARP_N 32
#define MITER (WARP_M / 16)   // 4
#define NITER (WARP_N / 8)    // 4

// ---------------- device scratch ----------------
__device__ int   g_tile_expert[MAX_TILES];
__device__ int   g_tile_row0[MAX_TILES];
__device__ int   g_tile_rows[MAX_TILES];
__device__ int   g_num_tiles;
__device__ float g_wr[(size_t)NEXP * DN * DK];   // tf32(RNA)-rounded weights

// ---------------- helpers ----------------
__device__ __forceinline__ uint32_t smem_u32(const void* p) {
    uint32_t a;
    asm("{ .reg .u64 t; cvta.to.shared.u64 t, %1; cvt.u32.u64 %0, t; }" : "=r"(a) : "l"(p));
    return a;
}
__device__ __forceinline__ void cp_async16(uint32_t dst, const void* src) {
    asm volatile("cp.async.cg.shared.global [%0], [%1], 16;" :: "r"(dst), "l"(src) : "memory");
}
__device__ __forceinline__ void cp_commit() {
    asm volatile("cp.async.commit_group;" ::: "memory");
}
__device__ __forceinline__ void cp_wait1() {
    asm volatile("cp.async.wait_group 1;" ::: "memory");
}
__device__ __forceinline__ float rna_tf32(float f) {
    uint32_t u = __float_as_uint(f), r;
    asm("cvt.rna.tf32.f32 %0, %1;" : "=r"(r) : "r"(u));
    return __uint_as_float(r);
}
__device__ __forceinline__ void ldsm_x4(uint32_t& r0, uint32_t& r1, uint32_t& r2, uint32_t& r3,
                                        uint32_t addr) {
    asm volatile("ldmatrix.sync.aligned.m8n8.x4.shared.b16 {%0,%1,%2,%3}, [%4];"
        : "=r"(r0), "=r"(r1), "=r"(r2), "=r"(r3) : "r"(addr));
}
__device__ __forceinline__ void mma_tf32(float& c0, float& c1, float& c2, float& c3,
                                         uint32_t a0, uint32_t a1, uint32_t a2, uint32_t a3,
                                         uint32_t b0, uint32_t b1) {
    asm volatile(
        "mma.sync.aligned.m16n8k8.row.col.f32.tf32.tf32.f32 "
        "{%0,%1,%2,%3}, {%4,%5,%6,%7}, {%8,%9}, {%0,%1,%2,%3};"
        : "+f"(c0), "+f"(c1), "+f"(c2), "+f"(c3)
        : "r"(a0), "r"(a1), "r"(a2), "r"(a3), "r"(b0), "r"(b1));
}

// ---------------- kernel 1: tile metadata ----------------
__global__ void meta_kernel(const void* __restrict__ freqv, int T) {
    if (threadIdx.x != 0 || blockIdx.x != 0) return;
    const int* f32p = (const int*)freqv;
    const long long* f64p = (const long long*)freqv;
    long long s32 = 0;
    for (int i = 0; i < NEXP; i++) s32 += f32p[i];
    const bool is64 = (s32 != (long long)T);
    int nt = 0, off = 0;
    for (int e = 0; e < NEXP; e++) {
        int c = is64 ? (int)f64p[e] : f32p[e];
        for (int r = 0; r < c; r += BM) {
            g_tile_expert[nt] = e;
            g_tile_row0[nt] = off + r;
            g_tile_rows[nt] = (c - r < BM) ? (c - r) : BM;
            nt++;
        }
        off += c;
    }
    g_num_tiles = nt;
}

// ---------------- kernel 2: weights fp32 -> tf32 (RNA, unbiased) ----------------
__global__ void round_w_kernel(const float4* __restrict__ w) {
    const int n4 = NEXP * DN * (DK / 4);
    float4* dst = reinterpret_cast<float4*>(g_wr);
    for (int i = blockIdx.x * blockDim.x + threadIdx.x; i < n4; i += gridDim.x * blockDim.x) {
        float4 v = w[i];
        v.x = rna_tf32(v.x); v.y = rna_tf32(v.y);
        v.z = rna_tf32(v.z); v.w = rna_tf32(v.w);
        dst[i] = v;
    }
}

// ---------------- kernel 3: grouped GEMM (tf32 mma.sync, 2 CTAs/SM) ----------
__global__ void __launch_bounds__(NTHREADS, 2) gemm_kernel(
    const float* __restrict__ x,      // [T, DK]  (truncated to tf32 by HMMA)
    const float* __restrict__ bias,   // [NEXP, DN]
    float* __restrict__ out,          // [T, DN]
    int T)
{
    extern __shared__ float smem[];
    float* As = smem;                               // [STAGES][BM][LDA]
    float* Bs = smem + STAGES * A_STAGE_F;          // [STAGES][BN][LDA]
    float* bias_s = Bs + STAGES * B_STAGE_F;        // [BN]

    const int tile = blockIdx.y;
    if (tile >= g_num_tiles) return;

    const int n0 = blockIdx.x * BN;
    const int e = g_tile_expert[tile];
    const int row0 = g_tile_row0[tile];
    const int rows = g_tile_rows[tile];

    const int tid = threadIdx.x;
    const int lane = tid & 31;
    const int wid = tid >> 5;
    const int warp_m = wid & 1;        // 0..1
    const int warp_n = wid >> 1;       // 0..3

    const uint32_t As_u = smem_u32(As);
    const uint32_t Bs_u = smem_u32(Bs);
    const float* __restrict__ wr = g_wr;

    if (tid < BN) bias_s[tid] = bias[e * DN + n0 + tid];

    // ldmatrix per-lane byte offsets (relative to stage base)
    // A x4: [r0-7,k0-3][r8-15,k0-3][r0-7,k4-7][r8-15,k4-7]
    const uint32_t a_lane_off =
        (uint32_t)(((warp_m * WARP_M + (lane & 15)) * LDA + (lane >> 4) * 4) * 4);
    // B x4: [n0-7,k0-3][n0-7,k4-7][n8-15,k0-3][n8-15,k4-7]
    const uint32_t b_lane_off =
        (uint32_t)(((warp_n * WARP_N + ((lane & 7) | ((lane >> 4) << 3))) * LDA
                    + ((lane >> 3) & 1) * 4) * 4);

    // ---- stage loader: A 1024 chunks + B 1024 chunks; 256 thr x (4+4) ----
    auto load_stage = [&](int st, int k0) {
        const uint32_t a_base = As_u + (uint32_t)st * A_STAGE_F * 4;
        const uint32_t b_base = Bs_u + (uint32_t)st * B_STAGE_F * 4;
        #pragma unroll
        for (int i = 0; i < 4; i++) {
            int c = tid + i * NTHREADS;
            int r = c >> 3, kc = c & 7;
            int gr = row0 + r; if (gr > T - 1) gr = T - 1;   // ragged tail clamp
            cp_async16(a_base + (uint32_t)(r * LDA + kc * 4) * 4,
                       x + (size_t)gr * DK + k0 + kc * 4);
        }
        #pragma unroll
        for (int i = 0; i < 4; i++) {
            int c = tid + i * NTHREADS;
            int r = c >> 3, kc = c & 7;
            cp_async16(b_base + (uint32_t)(r * LDA + kc * 4) * 4,
                       wr + (size_t)(e * DN + n0 + r) * DK + k0 + kc * 4);
        }
    };

    float acc[MITER][NITER][4];
    #pragma unroll
    for (int mi = 0; mi < MITER; mi++)
        #pragma unroll
        for (int ni = 0; ni < NITER; ni++)
            #pragma unroll
            for (int j = 0; j < 4; j++) acc[mi][ni][j] = 0.0f;

    #pragma unroll
    for (int s = 0; s < STAGES - 1; s++) {
        load_stage(s, s * BK);
        cp_commit();
    }

    for (int ks = 0; ks < NK; ks++) {
        cp_wait1();
        __syncthreads();

        int nxt = ks + STAGES - 1;
        if (nxt < NK) load_stage(nxt % STAGES, nxt * BK);
        cp_commit();

        const int st = ks % STAGES;
        const uint32_t AstU = As_u + (uint32_t)st * A_STAGE_F * 4;
        const uint32_t BstU = Bs_u + (uint32_t)st * B_STAGE_F * 4;

        #pragma unroll
        for (int kk = 0; kk < BK / 8; kk++) {
            const int k = kk * 8;
            uint32_t af[MITER][4];
            #pragma unroll
            for (int mi = 0; mi < MITER; mi++)
                ldsm_x4(af[mi][0], af[mi][1], af[mi][2], af[mi][3],
                        AstU + a_lane_off + (uint32_t)(mi * 16 * LDA + k) * 4);
            uint32_t bf[NITER][2];
            #pragma unroll
            for (int p = 0; p < NITER / 2; p++)
                ldsm_x4(bf[2 * p][0], bf[2 * p][1], bf[2 * p + 1][0], bf[2 * p + 1][1],
                        BstU + b_lane_off + (uint32_t)(p * 16 * LDA + k) * 4);
            #pragma unroll
            for (int mi = 0; mi < MITER; mi++)
                #pragma unroll
                for (int ni = 0; ni < NITER; ni++)
                    mma_tf32(acc[mi][ni][0], acc[mi][ni][1], acc[mi][ni][2], acc[mi][ni][3],
                             af[mi][0], af[mi][1], af[mi][2], af[mi][3],
                             bf[ni][0], bf[ni][1]);
        }
        // no trailing __syncthreads: stage ks%STAGES is only overwritten by loads
        // issued after the NEXT iteration's leading __syncthreads.
    }

    // ---- epilogue: bias add + masked store ----
    const int fr = lane >> 2;
    const int fc = lane & 3;
    #pragma unroll
    for (int mi = 0; mi < MITER; mi++) {
        const int r_lo = warp_m * WARP_M + mi * 16 + fr;
        const int r_hi = r_lo + 8;
        #pragma unroll
        for (int ni = 0; ni < NITER; ni++) {
            const int cn = warp_n * WARP_N + ni * 8 + 2 * fc;
            const float b0 = bias_s[cn], b1 = bias_s[cn + 1];
            if (r_lo < rows) {
                float2 v = {acc[mi][ni][0] + b0, acc[mi][ni][1] + b1};
                *reinterpret_cast<float2*>(out + (size_t)(row0 + r_lo) * DN + n0 + cn) = v;
            }
            if (r_hi < rows) {
                float2 v = {acc[mi][ni][2] + b0, acc[mi][ni][3] + b1};
                *reinterpret_cast<float2*>(out + (size_t)(row0 + r_hi) * DN + n0 + cn) = v;
            }
        }
    }
}

// ---------------- host ----------------
extern "C" void kernel_launch(void* const* d_in, const int* in_sizes, int n_in,
                              void* d_out, int out_size) {
    const float* x    = (const float*)d_in[0];
    const void*  freq = d_in[1];
    const float* w    = (const float*)d_in[2];
    const float* bias = (const float*)d_in[3];
    float* out = (float*)d_out;
    const int T = in_sizes[0] / DK;

    meta_kernel<<<1, 1>>>(freq, T);
    round_w_kernel<<<2048, 256>>>(reinterpret_cast<const float4*>(w));

    cudaFuncSetAttribute(gemm_kernel, cudaFuncAttributeMaxDynamicSharedMemorySize, SMEM_BYTES);
    dim3 grid(DN / BN, MAX_TILES);
    gemm_kernel<<<grid, NTHREADS, SMEM_BYTES>>>(x, bias, out, T);
    (void)n_in; (void)out_size;
}